// round 2
// baseline (speedup 1.0000x reference)
#include <cuda_runtime.h>
#include <cuda_bf16.h>

// Conv1d (valid cross-correlation) as implicit-im2col GEMM with tf32 mma.sync.
// x: [32, 64, 4096] f32   w: [128, 64, 64] f32   b: [128] f32
// out: [32, 128, 4033] f32
// out[n,f,t] = sum_c sum_j x[n,c,t+j] * w[f,c,j] + b[f]

#define N_BATCH 32
#define C_IN    64
#define W_IN    4096
#define F_OUT   128
#define WW      64
#define OUT_W   4033

#define M_BLK     128
#define WS_STRIDE 68        // 64 taps + 4 pad: makes B-fragment LDS conflict-free

__device__ __forceinline__ unsigned f2tf(float f) {
    unsigned u;
    asm("cvt.rna.tf32.f32 %0, %1;" : "=r"(u) : "f"(f));
    return u;
}

__global__ __launch_bounds__(256, 2)
void conv1d_tf32_kernel(const float* __restrict__ x,
                        const float* __restrict__ w,
                        const float* __restrict__ b,
                        float* __restrict__ out)
{
    __shared__ unsigned Ws[F_OUT * WS_STRIDE];  // tf32 bits of w[:, c, :]
    __shared__ unsigned Xs[208];                // tf32 bits of x[n, c, t0 .. t0+191]

    const int tid  = threadIdx.x;
    const int lane = tid & 31;
    const int warp = tid >> 5;
    const int wm   = warp & 1;    // 0..1  -> 64 rows (t) each
    const int wn   = warp >> 1;   // 0..3  -> 32 cols (f) each
    const int n    = blockIdx.y;
    const int t0   = blockIdx.x * M_BLK;

    const int q = lane >> 2;      // groupID      (0..7)
    const int r = lane & 3;       // threadInGroup (0..3)

    float acc[4][4][4];           // [mt][nt][c-frag]
    #pragma unroll
    for (int i = 0; i < 4; i++)
        #pragma unroll
        for (int j = 0; j < 4; j++)
            #pragma unroll
            for (int k = 0; k < 4; k++) acc[i][j][k] = 0.f;

    const float* xn = x + (size_t)n * C_IN * W_IN;
    const int m_base = wm * 64;
    const int n_base = wn * 32;

    for (int c = 0; c < C_IN; ++c) {
        // ---- stage x slice: 192 samples, zero-pad past W_IN ----
        if (tid < 192) {
            int t = t0 + tid;
            float v = (t < W_IN) ? xn[(size_t)c * W_IN + t] : 0.f;
            Xs[tid] = f2tf(v);
        }
        // ---- stage w[:, c, :] : 128 filters x 64 taps, as tf32 bits ----
        #pragma unroll
        for (int it = 0; it < 8; ++it) {
            int flat = tid + it * 256;            // 0..2047 float4 slots
            int f    = flat >> 4;                 // 0..127
            int j4   = flat & 15;                 // 0..15
            float4 v = __ldg((const float4*)(w + (size_t)f * (C_IN * WW) + c * WW + j4 * 4));
            unsigned* dst = &Ws[f * WS_STRIDE + j4 * 4];
            dst[0] = f2tf(v.x); dst[1] = f2tf(v.y);
            dst[2] = f2tf(v.z); dst[3] = f2tf(v.w);
        }
        __syncthreads();

        // ---- compute: 8 k-steps of 8 taps, 16 mmas each ----
        #pragma unroll
        for (int j0 = 0; j0 < WW; j0 += 8) {
            unsigned bb[4][2];
            #pragma unroll
            for (int nt = 0; nt < 4; ++nt) {
                int f = n_base + nt * 8 + q;
                bb[nt][0] = Ws[f * WS_STRIDE + j0 + r];
                bb[nt][1] = Ws[f * WS_STRIDE + j0 + r + 4];
            }
            #pragma unroll
            for (int mt = 0; mt < 4; ++mt) {
                int row = m_base + mt * 16 + q;
                // implicit im2col: A[m][k] = Xs[m + k]
                unsigned a0 = Xs[row     + j0 + r];
                unsigned a1 = Xs[row + 8 + j0 + r];
                unsigned a2 = Xs[row     + j0 + r + 4];
                unsigned a3 = Xs[row + 8 + j0 + r + 4];
                #pragma unroll
                for (int nt = 0; nt < 4; ++nt) {
                    asm volatile(
                        "mma.sync.aligned.m16n8k8.row.col.f32.tf32.tf32.f32 "
                        "{%0,%1,%2,%3}, {%4,%5,%6,%7}, {%8,%9}, {%0,%1,%2,%3};\n"
                        : "+f"(acc[mt][nt][0]), "+f"(acc[mt][nt][1]),
                          "+f"(acc[mt][nt][2]), "+f"(acc[mt][nt][3])
                        : "r"(a0), "r"(a1), "r"(a2), "r"(a3),
                          "r"(bb[nt][0]), "r"(bb[nt][1]));
                }
            }
        }
        __syncthreads();
    }

    // ---- epilogue: acc + bias -> out[n][f][t] ----
    float* outn = out + (size_t)n * F_OUT * OUT_W;
    #pragma unroll
    for (int mt = 0; mt < 4; ++mt) {
        int trow = t0 + m_base + mt * 16 + q;
        #pragma unroll
        for (int nt = 0; nt < 4; ++nt) {
            int f0 = n_base + nt * 8 + r * 2;
            float bias0 = __ldg(b + f0);
            float bias1 = __ldg(b + f0 + 1);
            if (trow < OUT_W) {
                outn[(size_t)f0       * OUT_W + trow] = acc[mt][nt][0] + bias0;
                outn[(size_t)(f0 + 1) * OUT_W + trow] = acc[mt][nt][1] + bias1;
            }
            if (trow + 8 < OUT_W) {
                outn[(size_t)f0       * OUT_W + trow + 8] = acc[mt][nt][2] + bias0;
                outn[(size_t)(f0 + 1) * OUT_W + trow + 8] = acc[mt][nt][3] + bias1;
            }
        }
    }
}

extern "C" void kernel_launch(void* const* d_in, const int* in_sizes, int n_in,
                              void* d_out, int out_size)
{
    const float* x = (const float*)d_in[0];
    const float* w = (const float*)d_in[1];
    const float* b = (const float*)d_in[2];
    float* out = (float*)d_out;

    dim3 grid((W_IN + M_BLK - 1) / M_BLK, N_BATCH);   // 32 x 32 blocks
    conv1d_tf32_kernel<<<grid, 256>>>(x, w, b, out);
}

// round 5
// speedup vs baseline: 1.0166x; 1.0166x over previous
#include <cuda_runtime.h>
#include <cstdint>

// Conv1d (valid cross-correlation) as implicit-im2col GEMM, tf32 mma.sync (HMMA path;
// tcgen05 is rejected by this toolchain: PTX is lowered for compute_103 without the
// 'a' feature set). Strategy: pre-convert x and w to tf32 bits once into __device__
// scratch, then a double-buffered cp.async pipeline keeps HMMA fed.
//
// x: [32, 64, 4096] f32   w: [128, 64, 64] f32   b: [128] f32
// out: [32, 128, 4033] f32,  out[n,f,t] = sum_c sum_j x[n,c,t+j] * w[f,c,j] + b[f]

#define N_BATCH 32
#define C_IN    64
#define W_IN    4096
#define F_OUT   128
#define WW      64
#define OUT_W   4033

#define M_BLK     128
#define WS_STRIDE 68          // 64 taps + 4 pad -> conflict-free B-fragment LDS
#define XPAD      4352        // padded x row: covers t0max(3968)+318, 16B-aligned rows

#define WS_U32    (F_OUT * WS_STRIDE)   // 8704 u32 per channel buffer
#define XS_U32    320                   // 128 + 128 + 64 halo
#define SMEM_BYTES (2 * WS_U32 * 4 + 2 * XS_U32 * 4)   // 72192

__device__ unsigned g_wtf[C_IN * F_OUT * WW];        // [c][f][j] tf32 bits (2 MB)
__device__ unsigned g_xtf[N_BATCH * C_IN * XPAD];    // [n][c][t] tf32 bits, zero-padded

__device__ __forceinline__ unsigned f2tf(float f) {
    unsigned u;
    asm("cvt.rna.tf32.f32 %0, %1;" : "=r"(u) : "f"(f));
    return u;
}

__global__ void prep_w(const float* __restrict__ w) {
    int idx = blockIdx.x * 256 + threadIdx.x;        // 524288 total
    int f = idx >> 12, c = (idx >> 6) & 63, j = idx & 63;
    g_wtf[(((c << 7) | f) << 6) | j] = f2tf(w[idx]);
}

__global__ void prep_x(const float* __restrict__ x) {
    int t   = blockIdx.x * 128 + threadIdx.x;
    int row = blockIdx.y;                            // n*64 + c
    if (t < XPAD) {
        float v = (t < W_IN) ? x[(size_t)row * W_IN + t] : 0.f;
        g_xtf[(size_t)row * XPAD + t] = f2tf(v);
    }
}

__device__ __forceinline__ void cpa16(uint32_t dst, const void* src) {
    asm volatile("cp.async.cg.shared.global [%0], [%1], 16;" :: "r"(dst), "l"(src) : "memory");
}
#define CPA_COMMIT() asm volatile("cp.async.commit_group;" ::: "memory")
#define CPA_WAIT1()  asm volatile("cp.async.wait_group 1;"  ::: "memory")

__global__ __launch_bounds__(256, 2)
void conv1d_main(const float* __restrict__ b, float* __restrict__ out)
{
    extern __shared__ unsigned sm[];
    const uint32_t smb = (uint32_t)__cvta_generic_to_shared(sm);

    const int tid  = threadIdx.x;
    const int lane = tid & 31;
    const int warp = tid >> 5;
    const int wm   = warp & 1;        // 2 warps along t  -> 64 rows each
    const int wn   = warp >> 1;       // 4 warps along f  -> 32 cols each
    const int n    = blockIdx.y;
    const int t0   = blockIdx.x * M_BLK;

    const int q = lane >> 2;          // 0..7
    const int r = lane & 3;           // 0..3
    const int m_base = wm * 64;
    const int n_base = wn * 32;

    float acc[4][4][4];
    #pragma unroll
    for (int i = 0; i < 4; i++)
        #pragma unroll
        for (int j = 0; j < 4; j++)
            #pragma unroll
            for (int k = 0; k < 4; k++) acc[i][j][k] = 0.f;

    const unsigned* xrow_base = g_xtf + (size_t)(n * C_IN) * XPAD + t0;

    // ---- async stage of one channel into buffer `buf` ----
    auto stage = [&](int c, int buf) {
        const unsigned* wsrc = g_wtf + ((size_t)c << 13);          // c * 8192
        uint32_t wdst = smb + (uint32_t)buf * (WS_U32 * 4);
        #pragma unroll
        for (int i = 0; i < 8; ++i) {
            int chunk = tid + (i << 8);                            // 0..2047
            int f = chunk >> 4, j4 = chunk & 15;
            cpa16(wdst + (uint32_t)(f * (WS_STRIDE * 4) + j4 * 16), wsrc + chunk * 4);
        }
        if (tid < 80) {
            const unsigned* xsrc = xrow_base + (size_t)c * XPAD + tid * 4;
            cpa16(smb + 2 * WS_U32 * 4 + (uint32_t)buf * (XS_U32 * 4) + tid * 16, xsrc);
        }
    };

    stage(0, 0);
    CPA_COMMIT();

    for (int c = 0; c < C_IN; ++c) {
        if (c + 1 < C_IN) stage(c + 1, (c + 1) & 1);
        CPA_COMMIT();
        CPA_WAIT1();                 // channel c resident
        __syncthreads();

        const unsigned* ws = sm + (c & 1) * WS_U32;
        const unsigned* xs = sm + 2 * WS_U32 + (c & 1) * XS_U32;

        #pragma unroll
        for (int j0 = 0; j0 < WW; j0 += 8) {
            unsigned bb[4][2];
            #pragma unroll
            for (int nt = 0; nt < 4; ++nt) {
                int f = n_base + nt * 8 + q;
                bb[nt][0] = ws[f * WS_STRIDE + j0 + r];
                bb[nt][1] = ws[f * WS_STRIDE + j0 + r + 4];
            }
            #pragma unroll
            for (int mt = 0; mt < 4; ++mt) {
                int row = m_base + mt * 16 + q;
                unsigned a0 = xs[row     + j0 + r];
                unsigned a1 = xs[row + 8 + j0 + r];
                unsigned a2 = xs[row     + j0 + r + 4];
                unsigned a3 = xs[row + 8 + j0 + r + 4];
                #pragma unroll
                for (int nt = 0; nt < 4; ++nt) {
                    asm volatile(
                        "mma.sync.aligned.m16n8k8.row.col.f32.tf32.tf32.f32 "
                        "{%0,%1,%2,%3}, {%4,%5,%6,%7}, {%8,%9}, {%0,%1,%2,%3};\n"
                        : "+f"(acc[mt][nt][0]), "+f"(acc[mt][nt][1]),
                          "+f"(acc[mt][nt][2]), "+f"(acc[mt][nt][3])
                        : "r"(a0), "r"(a1), "r"(a2), "r"(a3),
                          "r"(bb[nt][0]), "r"(bb[nt][1]));
                }
            }
        }
        __syncthreads();             // protect buf[c&1] before iter c+1 stages into it
    }

    // ---- epilogue: acc + bias -> out[n][f][t] ----
    float* outn = out + (size_t)n * F_OUT * OUT_W;
    #pragma unroll
    for (int mt = 0; mt < 4; ++mt) {
        int trow = t0 + m_base + mt * 16 + q;
        #pragma unroll
        for (int nt = 0; nt < 4; ++nt) {
            int f0 = n_base + nt * 8 + r * 2;
            float bias0 = __ldg(b + f0);
            float bias1 = __ldg(b + f0 + 1);
            if (trow < OUT_W) {
                outn[(size_t)f0       * OUT_W + trow] = acc[mt][nt][0] + bias0;
                outn[(size_t)(f0 + 1) * OUT_W + trow] = acc[mt][nt][1] + bias1;
            }
            if (trow + 8 < OUT_W) {
                outn[(size_t)f0       * OUT_W + trow + 8] = acc[mt][nt][2] + bias0;
                outn[(size_t)(f0 + 1) * OUT_W + trow + 8] = acc[mt][nt][3] + bias1;
            }
        }
    }
}

extern "C" void kernel_launch(void* const* d_in, const int* in_sizes, int n_in,
                              void* d_out, int out_size)
{
    const float* x = (const float*)d_in[0];
    const float* w = (const float*)d_in[1];
    const float* b = (const float*)d_in[2];
    float* out = (float*)d_out;

    prep_w<<<(C_IN * F_OUT * WW) / 256, 256>>>(w);
    prep_x<<<dim3(XPAD / 128, N_BATCH * C_IN), 128>>>(x);

    static int attr_done = 0;
    cudaFuncSetAttribute(conv1d_main,
                         cudaFuncAttributeMaxDynamicSharedMemorySize, SMEM_BYTES);
    (void)attr_done;

    dim3 grid(W_IN / M_BLK, N_BATCH);    // 32 x 32
    conv1d_main<<<grid, 256, SMEM_BYTES>>>(b, out);
}

// round 6
// speedup vs baseline: 2.0085x; 1.9757x over previous
#include <cuda_runtime.h>
#include <cuda_fp16.h>
#include <cstdint>

// Conv1d (valid cross-correlation) as implicit-im2col GEMM, fp16 mma.sync m16n8k16
// (fp32 accumulate). fp16 has the same 10-bit mantissa as tf32 (R2: rel_err 2.9e-4)
// but 2x the HMMA MAC rate and half the LDS per MAC.
//
// x: [32, 64, 4096] f32   w: [128, 64, 64] f32   b: [128] f32
// out: [32, 128, 4033] f32,  out[n,f,t] = sum_c sum_j x[n,c,t+j] * w[f,c,j] + b[f]
//
// Trick: A (im2col, sliding window) is read from a duplicated-pair array
// XsA[i] = half2(x[i], x[i+1]) so any window offset is one aligned LDS.32.

#define N_BATCH 32
#define C_IN    64
#define W_IN    4096
#define F_OUT   128
#define WW      64
#define OUT_W   4033

#define M_BLK   128
#define XPAD    4352          // padded x row (t0max 3968 + 319 halo < 4352)
#define S_W     72            // half-stride per filter: bank pattern 4q+r, conflict-free

__device__ __align__(16) half     g_wh[C_IN * F_OUT * WW];          // [c][f][j]  (1 MB)
__device__ __align__(16) unsigned g_xp[N_BATCH * C_IN * XPAD];      // half2 pairs (36 MB)

__global__ void prep_w(const float* __restrict__ w) {
    int idx = blockIdx.x * 256 + threadIdx.x;            // 524288
    int f = idx >> 12, c = (idx >> 6) & 63, j = idx & 63;
    g_wh[(((c << 7) | f) << 6) | j] = __float2half_rn(w[idx]);
}

__global__ void prep_x(const float* __restrict__ x) {
    int t   = blockIdx.x * 128 + threadIdx.x;
    int row = blockIdx.y;                                // n*64 + c
    if (t < XPAD) {
        const float* xr = x + (size_t)row * W_IN;
        float v0 = (t     < W_IN) ? xr[t]     : 0.f;
        float v1 = (t + 1 < W_IN) ? xr[t + 1] : 0.f;
        __half2 h = __floats2half2_rn(v0, v1);           // mem: [v0][v1]
        g_xp[(size_t)row * XPAD + t] = *(unsigned*)&h;
    }
}

__device__ __forceinline__ void cpa16(uint32_t dst, const void* src) {
    asm volatile("cp.async.cg.shared.global [%0], [%1], 16;" :: "r"(dst), "l"(src) : "memory");
}
__device__ __forceinline__ void cpa8(uint32_t dst, const void* src) {
    asm volatile("cp.async.ca.shared.global [%0], [%1], 8;" :: "r"(dst), "l"(src) : "memory");
}
#define CPA_COMMIT() asm volatile("cp.async.commit_group;" ::: "memory")
#define CPA_WAIT1()  asm volatile("cp.async.wait_group 1;"  ::: "memory")

__global__ __launch_bounds__(256, 2)
void conv1d_main(const float* __restrict__ b, float* __restrict__ out)
{
    __shared__ __align__(16) half     Wbuf[2][F_OUT * S_W];   // 2 x 18432 B
    __shared__ __align__(16) unsigned Xbuf[2][320];           // 2 x 1280 B

    const int tid  = threadIdx.x;
    const int lane = tid & 31;
    const int warp = tid >> 5;
    const int wm   = warp & 1;        // 2 warps along t -> 64 rows each
    const int wn   = warp >> 1;       // 4 warps along f -> 32 cols each
    const int n    = blockIdx.y;
    const int t0   = blockIdx.x * M_BLK;

    const int q = lane >> 2;          // 0..7
    const int r = lane & 3;           // 0..3
    const int m_base = wm * 64;
    const int n_base = wn * 32;

    float acc[4][4][4];
    #pragma unroll
    for (int i = 0; i < 4; i++)
        #pragma unroll
        for (int j = 0; j < 4; j++)
            #pragma unroll
            for (int k = 0; k < 4; k++) acc[i][j][k] = 0.f;

    const unsigned* xsrc_base = g_xp + (size_t)(n * C_IN) * XPAD + t0;
    const uint32_t wsm = (uint32_t)__cvta_generic_to_shared(Wbuf);
    const uint32_t xsm = (uint32_t)__cvta_generic_to_shared(Xbuf);

    auto stage = [&](int c, int buf) {
        const half* wsrc = g_wh + ((size_t)c << 13);          // c * 8192 halves
        uint32_t wdst = wsm + (uint32_t)buf * (F_OUT * S_W * 2);
        #pragma unroll
        for (int i = 0; i < 8; ++i) {
            int cidx = tid + (i << 8);                        // 0..2047 8-byte chunks
            int f = cidx >> 4, j8 = cidx & 15;
            cpa8(wdst + (uint32_t)(f * (S_W * 2) + j8 * 8), wsrc + f * 64 + j8 * 4);
        }
        if (tid < 80)
            cpa16(xsm + (uint32_t)buf * 1280 + tid * 16,
                  xsrc_base + (size_t)c * XPAD + tid * 4);
    };

    stage(0, 0);
    CPA_COMMIT();

    for (int c = 0; c < C_IN; ++c) {
        if (c + 1 < C_IN) stage(c + 1, (c + 1) & 1);
        CPA_COMMIT();
        CPA_WAIT1();
        __syncthreads();

        const half*     ws = Wbuf[c & 1];
        const unsigned* xa = Xbuf[c & 1];

        #pragma unroll
        for (int j0 = 0; j0 < WW; j0 += 16) {
            unsigned bb[4][2];
            #pragma unroll
            for (int nt = 0; nt < 4; ++nt) {
                const unsigned* wp =
                    (const unsigned*)(ws + (n_base + nt * 8 + q) * S_W + j0 + 2 * r);
                bb[nt][0] = wp[0];       // taps j0+2r, j0+2r+1
                bb[nt][1] = wp[4];       // taps j0+2r+8, j0+2r+9
            }
            #pragma unroll
            for (int mt = 0; mt < 4; ++mt) {
                int row = m_base + mt * 16 + q;
                unsigned a0 = xa[row     + j0 + 2 * r];
                unsigned a1 = xa[row + 8 + j0 + 2 * r];
                unsigned a2 = xa[row     + j0 + 2 * r + 8];
                unsigned a3 = xa[row + 8 + j0 + 2 * r + 8];
                #pragma unroll
                for (int nt = 0; nt < 4; ++nt) {
                    asm volatile(
                        "mma.sync.aligned.m16n8k16.row.col.f32.f16.f16.f32 "
                        "{%0,%1,%2,%3}, {%4,%5,%6,%7}, {%8,%9}, {%0,%1,%2,%3};\n"
                        : "+f"(acc[mt][nt][0]), "+f"(acc[mt][nt][1]),
                          "+f"(acc[mt][nt][2]), "+f"(acc[mt][nt][3])
                        : "r"(a0), "r"(a1), "r"(a2), "r"(a3),
                          "r"(bb[nt][0]), "r"(bb[nt][1]));
                }
            }
        }
        __syncthreads();   // protect buf (c&1) before stage(c+2) overwrites it
    }

    // ---- epilogue: acc + bias -> out[n][f][t] ----
    float* outn = out + (size_t)n * F_OUT * OUT_W;
    #pragma unroll
    for (int mt = 0; mt < 4; ++mt) {
        int trow = t0 + m_base + mt * 16 + q;
        #pragma unroll
        for (int nt = 0; nt < 4; ++nt) {
            int f0 = n_base + nt * 8 + r * 2;
            float bias0 = __ldg(b + f0);
            float bias1 = __ldg(b + f0 + 1);
            if (trow < OUT_W) {
                outn[(size_t)f0       * OUT_W + trow] = acc[mt][nt][0] + bias0;
                outn[(size_t)(f0 + 1) * OUT_W + trow] = acc[mt][nt][1] + bias1;
            }
            if (trow + 8 < OUT_W) {
                outn[(size_t)f0       * OUT_W + trow + 8] = acc[mt][nt][2] + bias0;
                outn[(size_t)(f0 + 1) * OUT_W + trow + 8] = acc[mt][nt][3] + bias1;
            }
        }
    }
}

extern "C" void kernel_launch(void* const* d_in, const int* in_sizes, int n_in,
                              void* d_out, int out_size)
{
    const float* x = (const float*)d_in[0];
    const float* w = (const float*)d_in[1];
    const float* b = (const float*)d_in[2];
    float* out = (float*)d_out;

    prep_w<<<(C_IN * F_OUT * WW) / 256, 256>>>(w);
    prep_x<<<dim3(XPAD / 128, N_BATCH * C_IN), 128>>>(x);

    dim3 grid(W_IN / M_BLK, N_BATCH);    // 32 x 32
    conv1d_main<<<grid, 256>>>(b, out);
}

// round 8
// speedup vs baseline: 2.0548x; 1.0231x over previous
#include <cuda_runtime.h>
#include <cuda_fp16.h>
#include <cstdint>

// Conv1d (valid cross-correlation) as implicit-im2col GEMM, fp16 mma.sync m16n8k16
// (fp32 accumulate), 4-deep cp.async ring with ONE barrier per channel.
//
// x: [32, 64, 4096] f32   w: [128, 64, 64] f32   b: [128] f32
// out: [32, 128, 4033] f32,  out[n,f,t] = sum_c sum_j x[n,c,t+j] * w[f,c,j] + b[f]

#define N_BATCH 32
#define C_IN    64
#define W_IN    4096
#define F_OUT   128
#define WW      64
#define OUT_W   4033

#define M_BLK   128
#define XPAD    4352          // padded x row (t0max 3968 + 319 halo < 4352)
#define S_W     72            // half-stride per filter: bank pattern 4q+r, conflict-free

#define W_TILE_B  (F_OUT * S_W * 2)          // 18432 B
#define X_TILE_B  (320 * 4)                  // 1280 B
#define RING_STRIDE (W_TILE_B + X_TILE_B)    // 19712 B (multiple of 128 -> banks keep)
#define SMEM_BYTES  (4 * RING_STRIDE)        // 78848 B

__device__ __align__(16) half     g_wh[C_IN * F_OUT * WW];          // [c][f][j]  (1 MB)
__device__ __align__(16) unsigned g_xp[N_BATCH * C_IN * XPAD];      // half2 pairs (36 MB)

// ---- merged prep: blocks [0,2048) convert w, [2048,36864) convert x ----
__global__ void prep_all(const float* __restrict__ w, const float* __restrict__ x) {
    int tid = threadIdx.x;
    int bid = blockIdx.x;
    if (bid < 2048) {
        int idx = bid * 256 + tid;                       // 524288 w elems
        int f = idx >> 12, c = (idx >> 6) & 63, j = idx & 63;
        g_wh[(((c << 7) | f) << 6) | j] = __float2half_rn(w[idx]);
    } else {
        int jb  = bid - 2048;                            // 0..34815
        int row = jb / 17;                               // n*64 + c
        int t   = (jb % 17) * 256 + tid;                 // 0..4351
        const float* xr = x + (size_t)row * W_IN;
        float v0 = (t     < W_IN) ? xr[t]     : 0.f;
        float v1 = (t + 1 < W_IN) ? xr[t + 1] : 0.f;
        __half2 h = __floats2half2_rn(v0, v1);
        g_xp[(size_t)row * XPAD + t] = *(unsigned*)&h;
    }
}

__device__ __forceinline__ void cpa16(uint32_t dst, const void* src) {
    asm volatile("cp.async.cg.shared.global [%0], [%1], 16;" :: "r"(dst), "l"(src) : "memory");
}
__device__ __forceinline__ void cpa8(uint32_t dst, const void* src) {
    asm volatile("cp.async.ca.shared.global [%0], [%1], 8;" :: "r"(dst), "l"(src) : "memory");
}
#define CPA_COMMIT() asm volatile("cp.async.commit_group;" ::: "memory")
#define CPA_WAIT2()  asm volatile("cp.async.wait_group 2;"  ::: "memory")

__global__ __launch_bounds__(256, 2)
void conv1d_main(const float* __restrict__ b, float* __restrict__ out)
{
    extern __shared__ __align__(16) char dsm[];
    const uint32_t smb = (uint32_t)__cvta_generic_to_shared(dsm);

    const int tid  = threadIdx.x;
    const int lane = tid & 31;
    const int warp = tid >> 5;
    const int wm   = warp & 1;        // 2 warps along t -> 64 rows each
    const int wn   = warp >> 1;       // 4 warps along f -> 32 cols each
    const int n    = blockIdx.y;
    const int t0   = blockIdx.x * M_BLK;

    const int q = lane >> 2;          // 0..7
    const int r = lane & 3;           // 0..3
    const int m_base = wm * 64;
    const int n_base = wn * 32;

    float acc[4][4][4];
    #pragma unroll
    for (int i = 0; i < 4; i++)
        #pragma unroll
        for (int j = 0; j < 4; j++)
            #pragma unroll
            for (int k = 0; k < 4; k++) acc[i][j][k] = 0.f;

    const unsigned* xsrc_base = g_xp + (size_t)(n * C_IN) * XPAD + t0;

    auto stage = [&](int c, int s) {
        const half* wsrc = g_wh + ((size_t)c << 13);          // c * 8192 halves
        uint32_t base = smb + (uint32_t)s * RING_STRIDE;
        #pragma unroll
        for (int i = 0; i < 8; ++i) {
            int cidx = tid + (i << 8);                        // 0..2047 8-byte chunks
            int f = cidx >> 4, j8 = cidx & 15;
            cpa8(base + (uint32_t)(f * (S_W * 2) + j8 * 8), wsrc + f * 64 + j8 * 4);
        }
        if (tid < 80)
            cpa16(base + W_TILE_B + tid * 16,
                  xsrc_base + (size_t)c * XPAD + tid * 4);
    };

    stage(0, 0); CPA_COMMIT();
    stage(1, 1); CPA_COMMIT();

    for (int c = 0; c < C_IN; ++c) {
        if (c + 2 < C_IN) stage(c + 2, (c + 2) & 3);
        CPA_COMMIT();
        CPA_WAIT2();                 // group c complete (c+1, c+2 may remain)
        __syncthreads();             // publish group c; also fences compute(c-1)
                                     //   before stage(c+3) next iter (4-deep ring)

        const char*     bufc = dsm + (c & 3) * RING_STRIDE;
        const half*     ws   = (const half*)bufc;
        const unsigned* xa   = (const unsigned*)(bufc + W_TILE_B);

        #pragma unroll
        for (int j0 = 0; j0 < WW; j0 += 16) {
            unsigned bb[4][2];
            #pragma unroll
            for (int nt = 0; nt < 4; ++nt) {
                const unsigned* wp =
                    (const unsigned*)(ws + (n_base + nt * 8 + q) * S_W + j0 + 2 * r);
                bb[nt][0] = wp[0];       // taps j0+2r, j0+2r+1
                bb[nt][1] = wp[4];       // taps j0+2r+8, j0+2r+9
            }
            #pragma unroll
            for (int mt = 0; mt < 4; ++mt) {
                int row = m_base + mt * 16 + q;
                unsigned a0 = xa[row     + j0 + 2 * r];
                unsigned a1 = xa[row + 8 + j0 + 2 * r];
                unsigned a2 = xa[row     + j0 + 2 * r + 8];
                unsigned a3 = xa[row + 8 + j0 + 2 * r + 8];
                #pragma unroll
                for (int nt = 0; nt < 4; ++nt) {
                    asm volatile(
                        "mma.sync.aligned.m16n8k16.row.col.f32.f16.f16.f32 "
                        "{%0,%1,%2,%3}, {%4,%5,%6,%7}, {%8,%9}, {%0,%1,%2,%3};\n"
                        : "+f"(acc[mt][nt][0]), "+f"(acc[mt][nt][1]),
                          "+f"(acc[mt][nt][2]), "+f"(acc[mt][nt][3])
                        : "r"(a0), "r"(a1), "r"(a2), "r"(a3),
                          "r"(bb[nt][0]), "r"(bb[nt][1]));
                }
            }
        }
    }

    // ---- epilogue: acc + bias -> out[n][f][t] ----
    float* outn = out + (size_t)n * F_OUT * OUT_W;
    #pragma unroll
    for (int mt = 0; mt < 4; ++mt) {
        int trow = t0 + m_base + mt * 16 + q;
        #pragma unroll
        for (int nt = 0; nt < 4; ++nt) {
            int f0 = n_base + nt * 8 + r * 2;
            float bias0 = __ldg(b + f0);
            float bias1 = __ldg(b + f0 + 1);
            if (trow < OUT_W) {
                outn[(size_t)f0       * OUT_W + trow] = acc[mt][nt][0] + bias0;
                outn[(size_t)(f0 + 1) * OUT_W + trow] = acc[mt][nt][1] + bias1;
            }
            if (trow + 8 < OUT_W) {
                outn[(size_t)f0       * OUT_W + trow + 8] = acc[mt][nt][2] + bias0;
                outn[(size_t)(f0 + 1) * OUT_W + trow + 8] = acc[mt][nt][3] + bias1;
            }
        }
    }
}

extern "C" void kernel_launch(void* const* d_in, const int* in_sizes, int n_in,
                              void* d_out, int out_size)
{
    const float* x = (const float*)d_in[0];
    const float* w = (const float*)d_in[1];
    const float* b = (const float*)d_in[2];
    float* out = (float*)d_out;

    prep_all<<<36864, 256>>>(w, x);

    cudaFuncSetAttribute(conv1d_main,
                         cudaFuncAttributeMaxDynamicSharedMemorySize, SMEM_BYTES);
    dim3 grid(W_IN / M_BLK, N_BATCH);    // 32 x 32
    conv1d_main<<<grid, 256, SMEM_BYTES>>>(b, out);
}

// round 11
// speedup vs baseline: 2.1949x; 1.0682x over previous
#include <cuda_runtime.h>
#include <cuda_fp16.h>
#include <cstdint>

// Conv1d (valid cross-correlation) as implicit-im2col GEMM, fp16 mma.sync m16n8k16
// (fp32 accumulate). 4-deep cp.async ring, mbarrier producer/consumer protocol,
// NO __syncthreads in the main loop (warps fully decoupled, drift bound = 3 ch).
//
// x: [32, 64, 4096] f32   w: [128, 64, 64] f32   b: [128] f32
// out: [32, 128, 4033] f32,  out[n,f,t] = sum_c sum_j x[n,c,t+j] * w[f,c,j] + b[f]

#define N_BATCH 32
#define C_IN    64
#define W_IN    4096
#define F_OUT   128
#define WW      64
#define OUT_W   4033

#define M_BLK   128
#define XPAD    4352          // padded x row (t0max 3968 + 319 halo < 4352)
#define S_W     72            // half-stride per filter: u32 bank pattern 4q+r, conflict-free

#define W_TILE_B  (F_OUT * S_W * 2)          // 18432 B
#define X_TILE_B  (320 * 4)                  // 1280 B
#define RING_STRIDE (W_TILE_B + X_TILE_B)    // 19712 B
#define MB_OFF      (4 * RING_STRIDE)        // 78848: full[4] then empty[4]
#define SMEM_BYTES  (MB_OFF + 64)

__device__ __align__(16) half     g_wh[C_IN * F_OUT * WW];          // [c][f][j]  (1 MB)
__device__ __align__(16) unsigned g_xp[N_BATCH * C_IN * XPAD];      // half2 pairs (36 MB)

// ---- merged prep: blocks [0,2048) convert w; rest convert x 4-wide ----
__global__ void prep_all(const float* __restrict__ w, const float* __restrict__ x) {
    int tid = threadIdx.x;
    int bid = blockIdx.x;
    if (bid < 2048) {
        int idx = bid * 256 + tid;                       // 524288 w elems
        int f = idx >> 12, c = (idx >> 6) & 63, j = idx & 63;
        g_wh[(((c << 7) | f) << 6) | j] = __float2half_rn(w[idx]);
    } else {
        int jb  = bid - 2048;                            // 5 blocks per row
        int row = jb / 5;                                // n*64 + c
        int t4  = ((jb % 5) * 256 + tid) * 4;
        if (t4 < XPAD) {
            uint4 o;
            if (t4 < W_IN) {                             // W_IN divisible by 4
                const float* xr = x + (size_t)row * W_IN;
                float4 v = *(const float4*)(xr + t4);
                float v4 = (t4 + 4 < W_IN) ? xr[t4 + 4] : 0.f;
                __half2 h0 = __floats2half2_rn(v.x, v.y);
                __half2 h1 = __floats2half2_rn(v.y, v.z);
                __half2 h2 = __floats2half2_rn(v.z, v.w);
                __half2 h3 = __floats2half2_rn(v.w, v4);
                o.x = *(unsigned*)&h0; o.y = *(unsigned*)&h1;
                o.z = *(unsigned*)&h2; o.w = *(unsigned*)&h3;
            } else {
                o.x = o.y = o.z = o.w = 0u;
            }
            *(uint4*)(g_xp + (size_t)row * XPAD + t4) = o;
        }
    }
}

// ---- async copy + mbarrier primitives ----
__device__ __forceinline__ void cpa16(uint32_t dst, const void* src) {
    asm volatile("cp.async.cg.shared.global [%0], [%1], 16;" :: "r"(dst), "l"(src) : "memory");
}
__device__ __forceinline__ void cpa8(uint32_t dst, const void* src) {
    asm volatile("cp.async.ca.shared.global [%0], [%1], 8;" :: "r"(dst), "l"(src) : "memory");
}
#define MBAR_INIT(addr, cnt) \
    asm volatile("mbarrier.init.shared.b64 [%0], %1;" :: "r"(addr), "r"(cnt) : "memory")
#define MBAR_ARRIVE(addr) \
    asm volatile("mbarrier.arrive.shared.b64 _, [%0];" :: "r"(addr) : "memory")
#define CP_MBAR_ARRIVE(addr) \
    asm volatile("cp.async.mbarrier.arrive.noinc.shared.b64 [%0];" :: "r"(addr) : "memory")

__device__ __forceinline__ void mbar_wait(uint32_t addr, uint32_t parity) {
    uint32_t done;
    asm volatile(
        "{\n\t.reg .pred p;\n\t"
        "mbarrier.try_wait.parity.shared.b64 p, [%1], %2;\n\t"
        "selp.b32 %0, 1, 0, p;\n\t}"
        : "=r"(done) : "r"(addr), "r"(parity) : "memory");
    if (!done) {
        asm volatile(
            "{\n\t.reg .pred P1;\n\t"
            "W_%=:\n\t"
            "mbarrier.try_wait.parity.shared.b64 P1, [%0], %1;\n\t"
            "@P1 bra.uni D_%=;\n\t"
            "bra.uni W_%=;\n\t"
            "D_%=:\n\t}"
            :: "r"(addr), "r"(parity) : "memory");
    }
}

__global__ __launch_bounds__(256, 2)
void conv1d_main(const float* __restrict__ b, float* __restrict__ out)
{
    extern __shared__ __align__(16) char dsm[];
    const uint32_t smb = (uint32_t)__cvta_generic_to_shared(dsm);

    const int tid  = threadIdx.x;
    const int lane = tid & 31;
    const int warp = tid >> 5;
    const int wm   = warp & 1;        // 2 warps along t -> 64 rows each
    const int wn   = warp >> 1;       // 4 warps along f -> 32 cols each
    const int n    = blockIdx.y;
    const int t0   = blockIdx.x * M_BLK;

    const int q = lane >> 2;          // 0..7
    const int r = lane & 3;           // 0..3
    const int m_base = wm * 64;
    const int n_base = wn * 32;

    float acc[4][4][4];
    #pragma unroll
    for (int i = 0; i < 4; i++)
        #pragma unroll
        for (int j = 0; j < 4; j++)
            #pragma unroll
            for (int k = 0; k < 4; k++) acc[i][j][k] = 0.f;

    const unsigned* xsrc_base = g_xp + (size_t)(n * C_IN) * XPAD + t0;

    // mbarriers: full[s] = staged data ready (256 cp.async thread-arrivals),
    //            empty[s] = all 8 warps done computing (8 arrivals)
    if (tid == 0) {
        #pragma unroll
        for (int s = 0; s < 4; ++s) {
            MBAR_INIT(smb + MB_OFF + s * 8, 256);
            MBAR_INIT(smb + MB_OFF + 32 + s * 8, 8);
        }
    }
    __syncthreads();   // the ONLY block-wide barrier

    auto stage = [&](int c, int s) {
        const half* wsrc = g_wh + ((size_t)c << 13);          // c * 8192 halves
        uint32_t base = smb + (uint32_t)s * RING_STRIDE;
        #pragma unroll
        for (int i = 0; i < 8; ++i) {
            int cidx = tid + (i << 8);                        // 0..2047 8-byte chunks
            int f = cidx >> 4, j8 = cidx & 15;
            cpa8(base + (uint32_t)(f * (S_W * 2) + j8 * 8), wsrc + f * 64 + j8 * 4);
        }
        if (tid < 80)
            cpa16(base + W_TILE_B + tid * 16,
                  xsrc_base + (size_t)c * XPAD + tid * 4);
        CP_MBAR_ARRIVE(smb + MB_OFF + s * 8);
    };

    stage(0, 0);
    stage(1, 1);
    stage(2, 2);

    for (int c = 0; c < C_IN; ++c) {
        mbar_wait(smb + MB_OFF + (c & 3) * 8, (c >> 2) & 1);   // data(c) ready

        const char*     bufc = dsm + (c & 3) * RING_STRIDE;
        const half*     ws   = (const half*)bufc;
        const unsigned* xa   = (const unsigned*)(bufc + W_TILE_B);

        #pragma unroll
        for (int j0 = 0; j0 < WW; j0 += 16) {
            unsigned bb[4][2];
            #pragma unroll
            for (int nt = 0; nt < 4; ++nt) {
                const unsigned* wp =
                    (const unsigned*)(ws + (n_base + nt * 8 + q) * S_W + j0 + 2 * r);
                bb[nt][0] = wp[0];       // taps j0+2r, j0+2r+1
                bb[nt][1] = wp[4];       // taps j0+2r+8, j0+2r+9
            }
            #pragma unroll
            for (int mt = 0; mt < 4; ++mt) {
                int row = m_base + mt * 16 + q;
                unsigned a0 = xa[row     + j0 + 2 * r];
                unsigned a1 = xa[row + 8 + j0 + 2 * r];
                unsigned a2 = xa[row     + j0 + 2 * r + 8];
                unsigned a3 = xa[row + 8 + j0 + 2 * r + 8];
                #pragma unroll
                for (int nt = 0; nt < 4; ++nt) {
                    asm volatile(
                        "mma.sync.aligned.m16n8k16.row.col.f32.f16.f16.f32 "
                        "{%0,%1,%2,%3}, {%4,%5,%6,%7}, {%8,%9}, {%0,%1,%2,%3};\n"
                        : "+f"(acc[mt][nt][0]), "+f"(acc[mt][nt][1]),
                          "+f"(acc[mt][nt][2]), "+f"(acc[mt][nt][3])
                        : "r"(a0), "r"(a1), "r"(a2), "r"(a3),
                          "r"(bb[nt][0]), "r"(bb[nt][1]));
                }
            }
        }

        if (lane == 0) MBAR_ARRIVE(smb + MB_OFF + 32 + (c & 3) * 8);  // warp done(c)

        // stage channel c+3 into buffer (c+3)&3 == (c-1)&3 (last used by channel c-1)
        if (c + 3 < C_IN) {
            if (c >= 1)   // wait: all warps done with channel c-1
                mbar_wait(smb + MB_OFF + 32 + ((c + 3) & 3) * 8, ((c - 1) >> 2) & 1);
            stage(c + 3, (c + 3) & 3);
        }
    }

    // ---- epilogue: acc + bias -> out[n][f][t] ----
    float* outn = out + (size_t)n * F_OUT * OUT_W;
    #pragma unroll
    for (int mt = 0; mt < 4; ++mt) {
        int trow = t0 + m_base + mt * 16 + q;
        #pragma unroll
        for (int nt = 0; nt < 4; ++nt) {
            int f0 = n_base + nt * 8 + r * 2;
            float bias0 = __ldg(b + f0);
            float bias1 = __ldg(b + f0 + 1);
            if (trow < OUT_W) {
                outn[(size_t)f0       * OUT_W + trow] = acc[mt][nt][0] + bias0;
                outn[(size_t)(f0 + 1) * OUT_W + trow] = acc[mt][nt][1] + bias1;
            }
            if (trow + 8 < OUT_W) {
                outn[(size_t)f0       * OUT_W + trow + 8] = acc[mt][nt][2] + bias0;
                outn[(size_t)(f0 + 1) * OUT_W + trow + 8] = acc[mt][nt][3] + bias1;
            }
        }
    }
}

extern "C" void kernel_launch(void* const* d_in, const int* in_sizes, int n_in,
                              void* d_out, int out_size)
{
    const float* x = (const float*)d_in[0];
    const float* w = (const float*)d_in[1];
    const float* b = (const float*)d_in[2];
    float* out = (float*)d_out;

    prep_all<<<2048 + 2048 * 5, 256>>>(w, x);

    cudaFuncSetAttribute(conv1d_main,
                         cudaFuncAttributeMaxDynamicSharedMemorySize, SMEM_BYTES);
    dim3 grid(W_IN / M_BLK, N_BATCH);    // 32 x 32
    conv1d_main<<<grid, 256, SMEM_BYTES>>>(b, out);
}

// round 12
// speedup vs baseline: 2.3877x; 1.0879x over previous
#include <cuda_runtime.h>
#include <cuda_fp16.h>
#include <cstdint>

// Conv1d (valid cross-correlation) as implicit-im2col GEMM, fp16 mma.sync m16n8k16
// (fp32 accumulate). 4-deep cp.async ring + mbarrier producer/consumer (no block
// barrier in main loop). This round: A fragments via LDS.64 from a duplicated-QUAD
// array (halves A LDS ops), w staged with 16B cp.async (halves LDGSTS ops).
//
// x: [32, 64, 4096] f32   w: [128, 64, 64] f32   b: [128] f32
// out: [32, 128, 4033] f32,  out[n,f,t] = sum_c sum_j x[n,c,t+j] * w[f,c,j] + b[f]

#define N_BATCH 32
#define C_IN    64
#define W_IN    4096
#define F_OUT   128
#define WW      64
#define OUT_W   4033

#define M_BLK   128
#define XPAD    4352          // padded x row (t0max 3968 + 319 halo < 4352)
#define S_W     72            // half-stride per filter: u32 bank pattern 4q+r, conflict-free

#define W_TILE_B  (F_OUT * S_W * 2)          // 18432 B
#define X_TILE_B  (320 * 8)                  // 2560 B (uint2 quads)
#define RING_STRIDE (W_TILE_B + X_TILE_B)    // 20992 B
#define MB_OFF      (4 * RING_STRIDE)        // 83968: full[4] then empty[4]
#define SMEM_BYTES  (MB_OFF + 64)

__device__ __align__(16) half  g_wh[C_IN * F_OUT * WW];        // [c][f][j]  (1 MB)
__device__ __align__(16) uint2 g_xq[N_BATCH * C_IN * XPAD];    // quads (71 MB)
// g_xq[row][i] = { half2(x[i],x[i+1]), half2(x[i+8],x[i+9]) }

// ---- merged prep: blocks [0,2048) convert w; rest build x quads (2 pos/thread) ----
__global__ void prep_all(const float* __restrict__ w, const float* __restrict__ x) {
    int tid = threadIdx.x;
    int bid = blockIdx.x;
    if (bid < 2048) {
        int idx = bid * 256 + tid;                       // 524288 w elems
        int f = idx >> 12, c = (idx >> 6) & 63, j = idx & 63;
        g_wh[(((c << 7) | f) << 6) | j] = __float2half_rn(w[idx]);
    } else {
        int jb  = bid - 2048;                            // 9 blocks per row
        int row = jb / 9;                                // n*64 + c
        int i   = ((jb % 9) * 256 + tid) * 2;            // even position
        if (i < XPAD) {
            const float* xr = x + (size_t)row * W_IN;
            float f0 = (i     < W_IN) ? xr[i]     : 0.f;
            float f1 = (i + 1 < W_IN) ? xr[i + 1] : 0.f;
            float f2 = (i + 2 < W_IN) ? xr[i + 2] : 0.f;
            float f8 = (i + 8 < W_IN) ? xr[i + 8] : 0.f;
            float f9 = (i + 9 < W_IN) ? xr[i + 9] : 0.f;
            float fA = (i + 10 < W_IN) ? xr[i + 10] : 0.f;
            __half2 a0 = __floats2half2_rn(f0, f1);
            __half2 a1 = __floats2half2_rn(f8, f9);
            __half2 b0 = __floats2half2_rn(f1, f2);
            __half2 b1 = __floats2half2_rn(f9, fA);
            uint4 o;
            o.x = *(unsigned*)&a0; o.y = *(unsigned*)&a1;
            o.z = *(unsigned*)&b0; o.w = *(unsigned*)&b1;
            *(uint4*)(g_xq + (size_t)row * XPAD + i) = o;
        }
    }
}

// ---- async copy + mbarrier primitives ----
__device__ __forceinline__ void cpa16(uint32_t dst, const void* src) {
    asm volatile("cp.async.cg.shared.global [%0], [%1], 16;" :: "r"(dst), "l"(src) : "memory");
}
#define MBAR_INIT(addr, cnt) \
    asm volatile("mbarrier.init.shared.b64 [%0], %1;" :: "r"(addr), "r"(cnt) : "memory")
#define MBAR_ARRIVE(addr) \
    asm volatile("mbarrier.arrive.shared.b64 _, [%0];" :: "r"(addr) : "memory")
#define CP_MBAR_ARRIVE(addr) \
    asm volatile("cp.async.mbarrier.arrive.noinc.shared.b64 [%0];" :: "r"(addr) : "memory")

__device__ __forceinline__ void mbar_wait(uint32_t addr, uint32_t parity) {
    uint32_t done;
    asm volatile(
        "{\n\t.reg .pred p;\n\t"
        "mbarrier.try_wait.parity.shared.b64 p, [%1], %2;\n\t"
        "selp.b32 %0, 1, 0, p;\n\t}"
        : "=r"(done) : "r"(addr), "r"(parity) : "memory");
    if (!done) {
        asm volatile(
            "{\n\t.reg .pred P1;\n\t"
            "W_%=:\n\t"
            "mbarrier.try_wait.parity.shared.b64 P1, [%0], %1;\n\t"
            "@P1 bra.uni D_%=;\n\t"
            "bra.uni W_%=;\n\t"
            "D_%=:\n\t}"
            :: "r"(addr), "r"(parity) : "memory");
    }
}

__global__ __launch_bounds__(256, 2)
void conv1d_main(const float* __restrict__ b, float* __restrict__ out)
{
    extern __shared__ __align__(16) char dsm[];
    const uint32_t smb = (uint32_t)__cvta_generic_to_shared(dsm);

    const int tid  = threadIdx.x;
    const int lane = tid & 31;
    const int warp = tid >> 5;
    const int wm   = warp & 1;        // 2 warps along t -> 64 rows each
    const int wn   = warp >> 1;       // 4 warps along f -> 32 cols each
    const int n    = blockIdx.y;
    const int t0   = blockIdx.x * M_BLK;

    const int q = lane >> 2;          // 0..7
    const int r = lane & 3;           // 0..3
    const int m_base = wm * 64;
    const int n_base = wn * 32;

    float acc[4][4][4];
    #pragma unroll
    for (int i = 0; i < 4; i++)
        #pragma unroll
        for (int j = 0; j < 4; j++)
            #pragma unroll
            for (int k = 0; k < 4; k++) acc[i][j][k] = 0.f;

    const uint2* xsrc_base = g_xq + (size_t)(n * C_IN) * XPAD + t0;

    // mbarriers: full[s] = staged data ready (256 cp.async thread-arrivals),
    //            empty[s] = all 8 warps done computing (8 arrivals)
    if (tid == 0) {
        #pragma unroll
        for (int s = 0; s < 4; ++s) {
            MBAR_INIT(smb + MB_OFF + s * 8, 256);
            MBAR_INIT(smb + MB_OFF + 32 + s * 8, 8);
        }
    }
    __syncthreads();   // the ONLY block-wide barrier

    auto stage = [&](int c, int s) {
        const half* wsrc = g_wh + ((size_t)c << 13);          // c * 8192 halves
        uint32_t base = smb + (uint32_t)s * RING_STRIDE;
        #pragma unroll
        for (int i = 0; i < 4; ++i) {
            int cidx = tid + (i << 8);                        // 0..1023 16-byte chunks
            int f = cidx >> 3, j16 = cidx & 7;
            cpa16(base + (uint32_t)(f * (S_W * 2) + j16 * 16), wsrc + f * 64 + j16 * 8);
        }
        if (tid < 160)
            cpa16(base + W_TILE_B + tid * 16,
                  (const char*)(xsrc_base + (size_t)c * XPAD) + tid * 16);
        CP_MBAR_ARRIVE(smb + MB_OFF + s * 8);
    };

    stage(0, 0);
    stage(1, 1);
    stage(2, 2);

    for (int c = 0; c < C_IN; ++c) {
        mbar_wait(smb + MB_OFF + (c & 3) * 8, (c >> 2) & 1);   // data(c) ready

        const char*  bufc = dsm + (c & 3) * RING_STRIDE;
        const half*  ws   = (const half*)bufc;
        const uint2* xa   = (const uint2*)(bufc + W_TILE_B);

        #pragma unroll
        for (int j0 = 0; j0 < WW; j0 += 16) {
            unsigned bb[4][2];
            #pragma unroll
            for (int nt = 0; nt < 4; ++nt) {
                const unsigned* wp =
                    (const unsigned*)(ws + (n_base + nt * 8 + q) * S_W + j0 + 2 * r);
                bb[nt][0] = wp[0];       // taps j0+2r, j0+2r+1
                bb[nt][1] = wp[4];       // taps j0+2r+8, j0+2r+9
            }
            #pragma unroll
            for (int mt = 0; mt < 4; ++mt) {
                int row = m_base + mt * 16 + q;
                // quads: one LDS.64 gives {pair(i), pair(i+8)}
                uint2 p01 = xa[row + j0 + 2 * r];        // a0, a1
                uint2 p23 = xa[row + j0 + 2 * r + 8];    // a2, a3
                #pragma unroll
                for (int nt = 0; nt < 4; ++nt) {
                    asm volatile(
                        "mma.sync.aligned.m16n8k16.row.col.f32.f16.f16.f32 "
                        "{%0,%1,%2,%3}, {%4,%5,%6,%7}, {%8,%9}, {%0,%1,%2,%3};\n"
                        : "+f"(acc[mt][nt][0]), "+f"(acc[mt][nt][1]),
                          "+f"(acc[mt][nt][2]), "+f"(acc[mt][nt][3])
                        : "r"(p01.x), "r"(p01.y), "r"(p23.x), "r"(p23.y),
                          "r"(bb[nt][0]), "r"(bb[nt][1]));
                }
            }
        }

        if (lane == 0) MBAR_ARRIVE(smb + MB_OFF + 32 + (c & 3) * 8);  // warp done(c)

        // stage channel c+3 into buffer (c+3)&3 == (c-1)&3 (last used by channel c-1)
        if (c + 3 < C_IN) {
            if (c >= 1)   // wait: all warps done with channel c-1
                mbar_wait(smb + MB_OFF + 32 + ((c + 3) & 3) * 8, ((c - 1) >> 2) & 1);
            stage(c + 3, (c + 3) & 3);
        }
    }

    // ---- epilogue: acc + bias -> out[n][f][t] ----
    float* outn = out + (size_t)n * F_OUT * OUT_W;
    #pragma unroll
    for (int mt = 0; mt < 4; ++mt) {
        int trow = t0 + m_base + mt * 16 + q;
        #pragma unroll
        for (int nt = 0; nt < 4; ++nt) {
            int f0 = n_base + nt * 8 + r * 2;
            float bias0 = __ldg(b + f0);
            float bias1 = __ldg(b + f0 + 1);
            if (trow < OUT_W) {
                outn[(size_t)f0       * OUT_W + trow] = acc[mt][nt][0] + bias0;
                outn[(size_t)(f0 + 1) * OUT_W + trow] = acc[mt][nt][1] + bias1;
            }
            if (trow + 8 < OUT_W) {
                outn[(size_t)f0       * OUT_W + trow + 8] = acc[mt][nt][2] + bias0;
                outn[(size_t)(f0 + 1) * OUT_W + trow + 8] = acc[mt][nt][3] + bias1;
            }
        }
    }
}

extern "C" void kernel_launch(void* const* d_in, const int* in_sizes, int n_in,
                              void* d_out, int out_size)
{
    const float* x = (const float*)d_in[0];
    const float* w = (const float*)d_in[1];
    const float* b = (const float*)d_in[2];
    float* out = (float*)d_out;

    prep_all<<<2048 + 2048 * 9, 256>>>(w, x);

    cudaFuncSetAttribute(conv1d_main,
                         cudaFuncAttributeMaxDynamicSharedMemorySize, SMEM_BYTES);
    dim3 grid(W_IN / M_BLK, N_BATCH);    // 32 x 32
    conv1d_main<<<grid, 256, SMEM_BYTES>>>(b, out);
}